// round 5
// baseline (speedup 1.0000x reference)
#include <cuda_runtime.h>
#include <math.h>

// Problem constants
#define TAU   0.07f
#define BB    8
#define CC    128
#define HH    512
#define WW    512
#define HWSZ  (HH*WW)
#define KK    64
#define NNEG  7
#define PP    4096
#define NQ    (BB*KK)          // 512
#define CPAD  68               // pool smem row stride (words)
#define NPB   128              // pool blocks (32 rows each)

// Device scratch (allocation-free)
__device__ float4 g_q[NQ * 32];          // RAW gathered queries [NQ][C]
__device__ float  g_pmax_val[NQ * NPB];  // per (query, pool-block) max dot*invp
__device__ float  g_partial[64];
__device__ int    g_done;

__device__ __forceinline__ void ffma2(unsigned long long& d,
                                      unsigned long long a,
                                      unsigned long long b) {
    asm("fma.rn.f32x2 %0, %1, %2, %0;" : "+l"(d) : "l"(a), "l"(b));
}

// ---------------------------------------------------------------------------
// Kernel 1: prep — PURE gather, TLB-friendly mapping.
// gid -> (k fastest, then c, then b): warp = fixed (b,c), lanes = k
// => all 32 loads of a warp hit ONE 2MB page. No reductions, no syncs.
// ---------------------------------------------------------------------------
__global__ void __launch_bounds__(256)
prep_kernel(const float* __restrict__ qf, const int* __restrict__ qidx) {
    int gid = blockIdx.x * 256 + threadIdx.x;   // 0..65535
    if (gid == 0) g_done = 0;
    int k = gid & 63;
    int c = (gid >> 6) & 127;
    int b = gid >> 13;
    int idx = qidx[b * KK + k];                 // coalesced
    float v = qf[(long)(b * CC + c) * HWSZ + idx];
    ((float*)g_q)[(b * KK + k) * CC + c] = v;   // raw, unnormalized
}

// ---------------------------------------------------------------------------
// Kernel 2: tiled GEMM + per-tile max, packed f32x2 FMA.
// grid = (128 pool-blocks, 8 query-blocks), 256 threads.
// Tile 64q x 32p; micro 4q x 2p (tx 0..15 -> p cols, ty 0..15 -> q rows).
// Pool staged RAW; invp computed in-block; stores max_p dot(q,p)*invp
// (query norm applied later in finalize).
// ---------------------------------------------------------------------------
__global__ void __launch_bounds__(256)
main_gemm_kernel(const float* __restrict__ pool) {
    __shared__ float q_s[64 * 64];      // 16 KB
    __shared__ float p_s[32 * CPAD];    // 8.5 KB
    __shared__ float invp_s[32];

    int t = threadIdx.x;
    int tx = t & 15, ty = t >> 4;       // tx 0..15, ty 0..15
    int pblk = blockIdx.x, qblk = blockIdx.y;
    int qbase = qblk * 64, pbase = pblk * 32;

    unsigned long long acc2[4][2];
    #pragma unroll
    for (int i = 0; i < 4; i++) { acc2[i][0] = 0ULL; acc2[i][1] = 0ULL; }

    float pss = 0.0f;                   // pool-row sumsq partial (row t>>3)

    for (int kc = 0; kc < 2; kc++) {
        if (kc) __syncthreads();
        // stage q: 64 rows x 16 float4 = 1024, 4 per thread (coalesced)
        #pragma unroll
        for (int it = 0; it < 4; it++) {
            int idx = t + it * 256;
            int r = idx >> 4, c4 = idx & 15;
            float4 v = g_q[(qbase + r) * 32 + kc * 16 + c4];
            *(float4*)(q_s + r * 64 + c4 * 4) = v;
        }
        // stage p raw: 32 rows x 16 float4 = 512, 2 per thread
        #pragma unroll
        for (int it = 0; it < 2; it++) {
            int idx = t + it * 256;
            int r = idx >> 4, c4 = idx & 15;
            float4 u = ((const float4*)pool)[(pbase + r) * 32 + kc * 16 + c4];
            *(float4*)(p_s + r * CPAD + c4 * 4) = u;
        }
        __syncthreads();

        // pool row sumsq: 8 threads per row, 2 float4 each
        {
            int r = t >> 3, h = t & 7;
            float s = 0.0f;
            #pragma unroll
            for (int j = 0; j < 2; j++) {
                float4 u = *(const float4*)(p_s + r * CPAD + (h * 2 + j) * 4);
                s += u.x*u.x + u.y*u.y + u.z*u.z + u.w*u.w;
            }
            #pragma unroll
            for (int o = 4; o > 0; o >>= 1) s += __shfl_xor_sync(0xFFFFFFFFu, s, o);
            pss += s;
        }

        // MMA: 4q x 2p micro-tile, packed f32x2
        #pragma unroll
        for (int c4 = 0; c4 < 16; c4++) {
            union F4 { float4 f; unsigned long long u[2]; } qv[4], pv[2];
            #pragma unroll
            for (int qi = 0; qi < 4; qi++)
                qv[qi].f = *(const float4*)(q_s + (ty * 4 + qi) * 64 + c4 * 4);
            #pragma unroll
            for (int pj = 0; pj < 2; pj++)
                pv[pj].f = *(const float4*)(p_s + (tx + 16 * pj) * CPAD + c4 * 4);
            #pragma unroll
            for (int qi = 0; qi < 4; qi++)
                #pragma unroll
                for (int pj = 0; pj < 2; pj++) {
                    ffma2(acc2[qi][pj], qv[qi].u[0], pv[pj].u[0]);
                    ffma2(acc2[qi][pj], qv[qi].u[1], pv[pj].u[1]);
                }
        }
    }

    if ((t & 7) == 0) invp_s[t >> 3] = 1.0f / fmaxf(sqrtf(pss), 1e-12f);
    __syncthreads();

    float inv0 = invp_s[tx], inv1 = invp_s[tx + 16];
    float bv[4];
    #pragma unroll
    for (int qi = 0; qi < 4; qi++) {
        float2 d0 = *(float2*)&acc2[qi][0];
        float2 d1 = *(float2*)&acc2[qi][1];
        bv[qi] = fmaxf((d0.x + d0.y) * inv0, (d1.x + d1.y) * inv1);
    }
    #pragma unroll
    for (int o = 8; o > 0; o >>= 1) {
        #pragma unroll
        for (int qi = 0; qi < 4; qi++)
            bv[qi] = fmaxf(bv[qi], __shfl_xor_sync(0xFFFFFFFFu, bv[qi], o));
    }
    if (tx == 0) {
        #pragma unroll
        for (int qi = 0; qi < 4; qi++)
            g_pmax_val[(qbase + ty * 4 + qi) * NPB + pblk] = bv[qi];
    }
}

// ---------------------------------------------------------------------------
// Kernel 3: finalize — warp per query: compute invq, max over 128 partials,
// negatives, softmax-CE; deterministic last-block mean. grid = 64 x 256.
// ---------------------------------------------------------------------------
__global__ void __launch_bounds__(256)
finalize_kernel(const float* __restrict__ negs, float* __restrict__ out) {
    __shared__ float loss_sm[8];
    int t = threadIdx.x, w = t >> 5, lane = t & 31;
    int q = blockIdx.x * 8 + w;
    int b = q >> 6, k = q & 63;

    // query inverse norm from raw gathered data
    float4 qv = g_q[q * 32 + lane];
    float qss = qv.x*qv.x + qv.y*qv.y + qv.z*qv.z + qv.w*qv.w;
    #pragma unroll
    for (int o = 16; o > 0; o >>= 1) qss += __shfl_xor_sync(0xFFFFFFFFu, qss, o);
    float invq = 1.0f / fmaxf(sqrtf(qss), 1e-12f);

    // max over 128 per-block partials (4 per lane)
    float v1 = fmaxf(fmaxf(g_pmax_val[q * NPB + lane],       g_pmax_val[q * NPB + 32 + lane]),
                     fmaxf(g_pmax_val[q * NPB + 64 + lane],  g_pmax_val[q * NPB + 96 + lane]));
    #pragma unroll
    for (int o = 16; o > 0; o >>= 1)
        v1 = fmaxf(v1, __shfl_xor_sync(0xFFFFFFFFu, v1, o));

    float l[1 + NNEG];
    l[0] = v1 * invq / TAU;

    #pragma unroll
    for (int n = 0; n < NNEG; n++) {
        const float4* np = (const float4*)(negs + (((long)(b * KK + k)) * NNEG + n) * CC);
        float4 nv = np[lane];
        float ss = nv.x*nv.x + nv.y*nv.y + nv.z*nv.z + nv.w*nv.w;
        float dt = nv.x*qv.x + nv.y*qv.y + nv.z*qv.z + nv.w*qv.w;
        #pragma unroll
        for (int o = 16; o > 0; o >>= 1) {
            ss += __shfl_xor_sync(0xFFFFFFFFu, ss, o);
            dt += __shfl_xor_sync(0xFFFFFFFFu, dt, o);
        }
        l[n + 1] = (dt * invq / fmaxf(sqrtf(ss), 1e-12f)) / TAU;
    }
    if (lane == 0) {
        float m = l[0];
        #pragma unroll
        for (int i = 1; i <= NNEG; i++) m = fmaxf(m, l[i]);
        float sum = 0.0f;
        #pragma unroll
        for (int i = 0; i <= NNEG; i++) sum += expf(l[i] - m);
        loss_sm[w] = m + logf(sum) - l[0];
    }
    __syncthreads();

    if (t == 0) {
        float s = 0.0f;
        #pragma unroll
        for (int i = 0; i < 8; i++) s += loss_sm[i];
        g_partial[blockIdx.x] = s;
        __threadfence();
        int ticket = atomicAdd(&g_done, 1);
        if (ticket == 63) {
            float tot = 0.0f;
            #pragma unroll
            for (int i = 0; i < 64; i++) tot += g_partial[i];
            out[0] = tot / (float)NQ;
        }
    }
}

extern "C" void kernel_launch(void* const* d_in, const int* in_sizes, int n_in,
                              void* d_out, int out_size) {
    const float* query_feat = (const float*)d_in[0];
    const float* pos_pool   = (const float*)d_in[1];
    const float* neg_protos = (const float*)d_in[2];
    const int*   query_idx  = (const int*)d_in[3];
    float* out = (float*)d_out;

    prep_kernel<<<256, 256>>>(query_feat, query_idx);
    dim3 grid(NPB, 8);
    main_gemm_kernel<<<grid, 256>>>(pos_pool);
    finalize_kernel<<<64, 256>>>(neg_protos, out);
}

// round 6
// speedup vs baseline: 1.0118x; 1.0118x over previous
#include <cuda_runtime.h>
#include <math.h>

// Problem constants
#define TAU   0.07f
#define BB    8
#define CC    128
#define HH    512
#define WW    512
#define HWSZ  (HH*WW)
#define KK    64
#define NNEG  7
#define PP    4096
#define NQ    (BB*KK)          // 512
#define CPAD  68               // pool smem row stride (words)
#define NPB   128              // pool blocks of 32 rows
#define NBLOCKS 512

// Device scratch (allocation-free)
__device__ float4 g_q[NQ * 32];          // RAW gathered queries [NQ][C]
__device__ float  g_pinv[PP];            // pool inverse norms
__device__ float  g_pmax_val[NQ * NPB];  // per (query, pool-block) max cos-sim*|q|
__device__ float  g_loss[NQ];
__device__ int    g_ticket;
__device__ volatile int g_bar_cnt;
__device__ volatile int g_bar_gen;

__device__ __forceinline__ void ffma2(unsigned long long& d,
                                      unsigned long long a,
                                      unsigned long long b) {
    asm("fma.rn.f32x2 %0, %1, %2, %0;" : "+l"(d) : "l"(a), "l"(b));
}

// Grid-wide barrier: safe because all NBLOCKS are co-resident (occupancy >= 4/SM).
__device__ __forceinline__ void grid_bar() {
    __syncthreads();
    if (threadIdx.x == 0) {
        int gen = g_bar_gen;
        __threadfence();
        if (atomicAdd((int*)&g_bar_cnt, 1) == NBLOCKS - 1) {
            g_bar_cnt = 0;
            __threadfence();
            g_bar_gen = gen + 1;
        } else {
            while (g_bar_gen == gen) { __nanosleep(64); }
        }
    }
    __syncthreads();
}

__global__ void __launch_bounds__(256, 4)
fused_kernel(const float* __restrict__ qf,
             const float* __restrict__ pool,
             const float* __restrict__ negs,
             const int*   __restrict__ qidx,
             float* __restrict__ out) {
    __shared__ float q_s[64 * 64];      // 16 KB
    __shared__ float p_s[32 * CPAD];    // 8.5 KB
    __shared__ float fin_dt[8], fin_ss[8];
    __shared__ int   s_last;

    int t = threadIdx.x;
    int bid = blockIdx.x;
    int w = t >> 5, lane = t & 31;

    if (bid == 0 && t == 0) g_ticket = 0;   // replay-safe reset (before barrier #1)

    // ================= Phase A: gather (warps 0-3) + pool norms (warps 4-7) ===
    if (w < 4) {
        // 128 gathered elements per block: e = bid*128 + t  (t < 128)
        int e = bid * 128 + t;
        int k = e & 63;
        int c = (e >> 6) & 127;
        int b = e >> 13;
        int idx = qidx[b * KK + k];
        float v = qf[(long)(b * CC + c) * HWSZ + idx];
        ((float*)g_q)[(b * KK + k) * CC + c] = v;
    } else {
        // pool inverse norms: warp (w-4) handles rows bid*8 + (w-4)*2 + {0,1}
        #pragma unroll
        for (int j = 0; j < 2; j++) {
            int r = bid * 8 + (w - 4) * 2 + j;
            float4 u = ((const float4*)pool)[r * 32 + lane];
            float ss = u.x*u.x + u.y*u.y + u.z*u.z + u.w*u.w;
            #pragma unroll
            for (int o = 16; o > 0; o >>= 1) ss += __shfl_xor_sync(0xFFFFFFFFu, ss, o);
            if (lane == 0) g_pinv[r] = 1.0f / fmaxf(sqrtf(ss), 1e-12f);
        }
    }

    grid_bar();

    // ================= Phase B: GEMM, 2 tiles of 64q x 32p per block ==========
    int tx = t & 15, ty = t >> 4;
    #pragma unroll
    for (int tile = 0; tile < 2; tile++) {
        int tid2 = bid + tile * NBLOCKS;     // 0..1023
        int pblk = tid2 & 127, qblk = tid2 >> 7;
        int qbase = qblk * 64, pbase = pblk * 32;

        unsigned long long acc2[4][2];
        #pragma unroll
        for (int i = 0; i < 4; i++) { acc2[i][0] = 0ULL; acc2[i][1] = 0ULL; }

        for (int kc = 0; kc < 2; kc++) {
            __syncthreads();
            #pragma unroll
            for (int it = 0; it < 4; it++) {
                int idx = t + it * 256;
                int r = idx >> 4, c4 = idx & 15;
                float4 v = g_q[(qbase + r) * 32 + kc * 16 + c4];
                *(float4*)(q_s + r * 64 + c4 * 4) = v;
            }
            #pragma unroll
            for (int it = 0; it < 2; it++) {
                int idx = t + it * 256;
                int r = idx >> 4, c4 = idx & 15;
                float4 u = ((const float4*)pool)[(pbase + r) * 32 + kc * 16 + c4];
                float s = g_pinv[pbase + r];
                u.x *= s; u.y *= s; u.z *= s; u.w *= s;
                *(float4*)(p_s + r * CPAD + c4 * 4) = u;
            }
            __syncthreads();

            #pragma unroll
            for (int c4 = 0; c4 < 16; c4++) {
                union F4 { float4 f; unsigned long long u[2]; } qv[4], pv[2];
                #pragma unroll
                for (int qi = 0; qi < 4; qi++)
                    qv[qi].f = *(const float4*)(q_s + (ty * 4 + qi) * 64 + c4 * 4);
                #pragma unroll
                for (int pj = 0; pj < 2; pj++)
                    pv[pj].f = *(const float4*)(p_s + (tx + 16 * pj) * CPAD + c4 * 4);
                #pragma unroll
                for (int qi = 0; qi < 4; qi++)
                    #pragma unroll
                    for (int pj = 0; pj < 2; pj++) {
                        ffma2(acc2[qi][pj], qv[qi].u[0], pv[pj].u[0]);
                        ffma2(acc2[qi][pj], qv[qi].u[1], pv[pj].u[1]);
                    }
            }
        }

        float bv[4];
        #pragma unroll
        for (int qi = 0; qi < 4; qi++) {
            float2 d0 = *(float2*)&acc2[qi][0];
            float2 d1 = *(float2*)&acc2[qi][1];
            bv[qi] = fmaxf(d0.x + d0.y, d1.x + d1.y);
        }
        #pragma unroll
        for (int o = 8; o > 0; o >>= 1) {
            #pragma unroll
            for (int qi = 0; qi < 4; qi++)
                bv[qi] = fmaxf(bv[qi], __shfl_xor_sync(0xFFFFFFFFu, bv[qi], o));
        }
        if (tx == 0) {
            #pragma unroll
            for (int qi = 0; qi < 4; qi++)
                g_pmax_val[(qbase + ty * 4 + qi) * NPB + pblk] = bv[qi];
        }
    }

    grid_bar();

    // ================= Phase C: finalize, one query per block ================
    {
        int q = bid;
        int b = q >> 6, k = q & 63;

        if (w < NNEG) {
            // warp w: negative w — dot & sumsq
            const float4* np = (const float4*)(negs + (((long)(b * KK + k)) * NNEG + w) * CC);
            float4 nv = np[lane];
            float4 qv = g_q[q * 32 + lane];
            float ss = nv.x*nv.x + nv.y*nv.y + nv.z*nv.z + nv.w*nv.w;
            float dt = nv.x*qv.x + nv.y*qv.y + nv.z*qv.z + nv.w*qv.w;
            #pragma unroll
            for (int o = 16; o > 0; o >>= 1) {
                ss += __shfl_xor_sync(0xFFFFFFFFu, ss, o);
                dt += __shfl_xor_sync(0xFFFFFFFFu, dt, o);
            }
            if (lane == 0) { fin_dt[w] = dt; fin_ss[w] = ss; }
        } else {
            // warp 7: query inv-norm + max over 128 pool-block partials
            float4 qv = g_q[q * 32 + lane];
            float qss = qv.x*qv.x + qv.y*qv.y + qv.z*qv.z + qv.w*qv.w;
            float v1 = fmaxf(fmaxf(g_pmax_val[q * NPB + lane],      g_pmax_val[q * NPB + 32 + lane]),
                             fmaxf(g_pmax_val[q * NPB + 64 + lane], g_pmax_val[q * NPB + 96 + lane]));
            #pragma unroll
            for (int o = 16; o > 0; o >>= 1) {
                qss += __shfl_xor_sync(0xFFFFFFFFu, qss, o);
                v1 = fmaxf(v1, __shfl_xor_sync(0xFFFFFFFFu, v1, o));
            }
            if (lane == 0) {
                fin_dt[7] = v1;
                fin_ss[7] = 1.0f / fmaxf(sqrtf(qss), 1e-12f);   // invq
            }
        }
        __syncthreads();

        if (t == 0) {
            float invq = fin_ss[7];
            float l[1 + NNEG];
            l[0] = fin_dt[7] * invq / TAU;
            #pragma unroll
            for (int n = 0; n < NNEG; n++)
                l[n + 1] = (fin_dt[n] * invq / fmaxf(sqrtf(fin_ss[n]), 1e-12f)) / TAU;
            float m = l[0];
            #pragma unroll
            for (int i = 1; i <= NNEG; i++) m = fmaxf(m, l[i]);
            float sum = 0.0f;
            #pragma unroll
            for (int i = 0; i <= NNEG; i++) sum += expf(l[i] - m);
            g_loss[q] = m + logf(sum) - l[0];
            __threadfence();
            int tk = atomicAdd(&g_ticket, 1);
            s_last = (tk == NBLOCKS - 1) ? 1 : 0;
        }
        __syncthreads();

        // last-arriving block: deterministic fixed-order mean over 512 losses
        if (s_last) {
            __shared__ float red[256];
            red[t] = g_loss[t] + g_loss[t + 256];
            __syncthreads();
            #pragma unroll
            for (int s = 128; s >= 1; s >>= 1) {
                if (t < s) red[t] += red[t + s];
                __syncthreads();
            }
            if (t == 0) out[0] = red[0] / (float)NQ;
        }
    }
}

extern "C" void kernel_launch(void* const* d_in, const int* in_sizes, int n_in,
                              void* d_out, int out_size) {
    const float* query_feat = (const float*)d_in[0];
    const float* pos_pool   = (const float*)d_in[1];
    const float* neg_protos = (const float*)d_in[2];
    const int*   query_idx  = (const int*)d_in[3];
    float* out = (float*)d_out;

    fused_kernel<<<NBLOCKS, 256>>>(query_feat, pos_pool, neg_protos, query_idx, out);
}

// round 7
// speedup vs baseline: 1.2372x; 1.2227x over previous
#include <cuda_runtime.h>
#include <math.h>

// Problem constants
#define TAU   0.07f
#define BB    8
#define CC    128
#define HH    512
#define WW    512
#define HWSZ  (HH*WW)
#define KK    64
#define NNEG  7
#define PP    4096
#define NQ    (BB*KK)          // 512
#define CPAD  68               // pool smem row stride (words)
#define NPB   64               // pool blocks of 64 rows

// Device scratch (allocation-free)
__device__ float4 g_q[NQ * 32];          // RAW gathered queries [NQ][C]
__device__ float  g_pinv[PP];            // pool inverse norms
__device__ float  g_pmax_val[NQ * NPB];  // per (query,pool-block) max cos*|q|
__device__ float  g_loss[NQ];
__device__ int    g_ticket;

__device__ __forceinline__ void ffma2(unsigned long long& d,
                                      unsigned long long a,
                                      unsigned long long b) {
    asm("fma.rn.f32x2 %0, %1, %2, %0;" : "+l"(d) : "l"(a), "l"(b));
}

// ---------------------------------------------------------------------------
// Kernel 1: gather (1 scattered element/thread, TLB-friendly: warp = one
// (b,c) page, lanes = k) + pool inverse norms (2 rows per warp) + ticket reset.
// 256 blocks x 256 threads.
// ---------------------------------------------------------------------------
__global__ void __launch_bounds__(256)
prep_kernel(const float* __restrict__ qf,
            const float* __restrict__ pool,
            const int*   __restrict__ qidx) {
    int t = threadIdx.x, bid = blockIdx.x;
    int w = t >> 5, lane = t & 31;
    if (bid == 0 && t == 0) g_ticket = 0;

    // scattered gather: e -> (k fastest, c, b); warp stays in one 2MB page
    int e = bid * 256 + t;
    int k = e & 63;
    int c = (e >> 6) & 127;
    int b = e >> 13;
    int idx = qidx[b * KK + k];
    float v = qf[(long)(b * CC + c) * HWSZ + idx];

    // pool inverse norms: warp w handles rows bid*16 + w*2 + {0,1}
    #pragma unroll
    for (int j = 0; j < 2; j++) {
        int r = bid * 16 + w * 2 + j;
        float4 u = ((const float4*)pool)[r * 32 + lane];
        float ss = u.x*u.x + u.y*u.y + u.z*u.z + u.w*u.w;
        #pragma unroll
        for (int o = 16; o > 0; o >>= 1) ss += __shfl_xor_sync(0xFFFFFFFFu, ss, o);
        if (lane == 0) g_pinv[r] = 1.0f / fmaxf(sqrtf(ss), 1e-12f);
    }

    ((float*)g_q)[(b * KK + k) * CC + c] = v;
}

// ---------------------------------------------------------------------------
// Kernel 2: GEMM + per-tile max. grid = (64 pblk, 8 qblk), 128 threads.
// Tile 64q x 64p; micro 8q x 4p. tx = t&15 -> p cols {tx,tx+16,tx+32,tx+48};
// ty = t>>4 (0..7) -> q rows ty*8..+7 (q reads are 16-lane broadcasts).
// Pool rows scaled by g_pinv at staging; stores max_p cos(q,p)*|q|.
// ---------------------------------------------------------------------------
__global__ void __launch_bounds__(128)
gemm_kernel(const float* __restrict__ pool) {
    __shared__ float q_s[64 * 64];      // 16 KB
    __shared__ float p_s[64 * CPAD];    // 17.4 KB

    int t = threadIdx.x;
    int tx = t & 15, ty = t >> 4;
    int pblk = blockIdx.x, qblk = blockIdx.y;
    int qbase = qblk * 64, pbase = pblk * 64;

    unsigned long long acc2[8][4];
    #pragma unroll
    for (int i = 0; i < 8; i++)
        #pragma unroll
        for (int j = 0; j < 4; j++) acc2[i][j] = 0ULL;

    for (int kc = 0; kc < 2; kc++) {
        if (kc) __syncthreads();
        // stage: 1024 float4 each tensor, 8 per thread, coalesced
        #pragma unroll
        for (int it = 0; it < 8; it++) {
            int idx = t + it * 128;
            int r = idx >> 4, c4 = idx & 15;
            float4 v = g_q[(qbase + r) * 32 + kc * 16 + c4];
            *(float4*)(q_s + r * 64 + c4 * 4) = v;
            float4 u = ((const float4*)pool)[(pbase + r) * 32 + kc * 16 + c4];
            float s = g_pinv[pbase + r];
            u.x *= s; u.y *= s; u.z *= s; u.w *= s;
            *(float4*)(p_s + r * CPAD + c4 * 4) = u;
        }
        __syncthreads();

        #pragma unroll
        for (int c4 = 0; c4 < 16; c4++) {
            union F4 { float4 f; unsigned long long u[2]; } qv, pv[4];
            #pragma unroll
            for (int pj = 0; pj < 4; pj++)
                pv[pj].f = *(const float4*)(p_s + (tx + 16 * pj) * CPAD + c4 * 4);
            #pragma unroll
            for (int qi = 0; qi < 8; qi++) {
                qv.f = *(const float4*)(q_s + (ty * 8 + qi) * 64 + c4 * 4);
                #pragma unroll
                for (int pj = 0; pj < 4; pj++) {
                    ffma2(acc2[qi][pj], qv.u[0], pv[pj].u[0]);
                    ffma2(acc2[qi][pj], qv.u[1], pv[pj].u[1]);
                }
            }
        }
    }

    // epilogue: per-thread max over its 4 p cols, then 16-lane max reduce
    float bv[8];
    #pragma unroll
    for (int qi = 0; qi < 8; qi++) {
        float2 d0 = *(float2*)&acc2[qi][0];
        float2 d1 = *(float2*)&acc2[qi][1];
        float2 d2 = *(float2*)&acc2[qi][2];
        float2 d3 = *(float2*)&acc2[qi][3];
        bv[qi] = fmaxf(fmaxf(d0.x + d0.y, d1.x + d1.y),
                       fmaxf(d2.x + d2.y, d3.x + d3.y));
    }
    #pragma unroll
    for (int o = 8; o > 0; o >>= 1) {
        #pragma unroll
        for (int qi = 0; qi < 8; qi++)
            bv[qi] = fmaxf(bv[qi], __shfl_xor_sync(0xFFFFFFFFu, bv[qi], o));
    }
    if (tx == 0) {
        #pragma unroll
        for (int qi = 0; qi < 8; qi++)
            g_pmax_val[(qbase + ty * 8 + qi) * NPB + pblk] = bv[qi];
    }
}

// ---------------------------------------------------------------------------
// Kernel 3: finalize — warp per query: invq, max over 64 partials, negatives,
// softmax-CE; ticket-elected deterministic mean. grid = 64 x 256.
// ---------------------------------------------------------------------------
__global__ void __launch_bounds__(256)
finalize_kernel(const float* __restrict__ negs, float* __restrict__ out) {
    __shared__ float loss_sm[8];
    __shared__ int   s_last;
    int t = threadIdx.x, w = t >> 5, lane = t & 31;
    int q = blockIdx.x * 8 + w;
    int b = q >> 6, k = q & 63;

    float4 qv = g_q[q * 32 + lane];
    float qss = qv.x*qv.x + qv.y*qv.y + qv.z*qv.z + qv.w*qv.w;
    float v1 = fmaxf(g_pmax_val[q * NPB + lane], g_pmax_val[q * NPB + 32 + lane]);
    #pragma unroll
    for (int o = 16; o > 0; o >>= 1) {
        qss += __shfl_xor_sync(0xFFFFFFFFu, qss, o);
        v1 = fmaxf(v1, __shfl_xor_sync(0xFFFFFFFFu, v1, o));
    }
    float invq = 1.0f / fmaxf(sqrtf(qss), 1e-12f);

    float l[1 + NNEG];
    l[0] = v1 * invq / TAU;

    #pragma unroll
    for (int n = 0; n < NNEG; n++) {
        const float4* np = (const float4*)(negs + (((long)(b * KK + k)) * NNEG + n) * CC);
        float4 nv = np[lane];
        float ss = nv.x*nv.x + nv.y*nv.y + nv.z*nv.z + nv.w*nv.w;
        float dt = nv.x*qv.x + nv.y*qv.y + nv.z*qv.z + nv.w*qv.w;
        #pragma unroll
        for (int o = 16; o > 0; o >>= 1) {
            ss += __shfl_xor_sync(0xFFFFFFFFu, ss, o);
            dt += __shfl_xor_sync(0xFFFFFFFFu, dt, o);
        }
        l[n + 1] = (dt * invq / fmaxf(sqrtf(ss), 1e-12f)) / TAU;
    }
    if (lane == 0) {
        float m = l[0];
        #pragma unroll
        for (int i = 1; i <= NNEG; i++) m = fmaxf(m, l[i]);
        float sum = 0.0f;
        #pragma unroll
        for (int i = 0; i <= NNEG; i++) sum += expf(l[i] - m);
        loss_sm[w] = m + logf(sum) - l[0];
    }
    __syncthreads();

    if (t == 0) {
        float s = 0.0f;
        #pragma unroll
        for (int i = 0; i < 8; i++) s += loss_sm[i];
        g_loss[blockIdx.x] = s;          // per-block partial (8 queries)
        __threadfence();
        int tk = atomicAdd(&g_ticket, 1);
        s_last = (tk == 63) ? 1 : 0;
    }
    __syncthreads();

    if (s_last) {
        // last block: deterministic fixed-order mean over 64 partials
        if (w == 0) {
            float v = (lane < 32) ? g_loss[lane] : 0.0f;
            float v2 = g_loss[lane + 32];
            float s = v + v2;
            #pragma unroll
            for (int o = 16; o > 0; o >>= 1) s += __shfl_xor_sync(0xFFFFFFFFu, s, o);
            if (lane == 0) out[0] = s / (float)NQ;
        }
    }
}

extern "C" void kernel_launch(void* const* d_in, const int* in_sizes, int n_in,
                              void* d_out, int out_size) {
    const float* query_feat = (const float*)d_in[0];
    const float* pos_pool   = (const float*)d_in[1];
    const float* neg_protos = (const float*)d_in[2];
    const int*   query_idx  = (const int*)d_in[3];
    float* out = (float*)d_out;

    prep_kernel<<<256, 256>>>(query_feat, pos_pool, query_idx);
    dim3 grid(NPB, 8);
    gemm_kernel<<<grid, 128>>>(pos_pool);
    finalize_kernel<<<64, 256>>>(neg_protos, out);
}